// round 5
// baseline (speedup 1.0000x reference)
#include <cuda_runtime.h>

// Problem constants (from reference): B=8192, N=4, C=4096
#define C_DIM   4096
#define N_DIM   4
#define THREADS 1024
#define F4_PER_ROW (C_DIM / 4)      // 1024 float4 per (b,n) row == THREADS
#define EPS 1e-6f

__global__ void __launch_bounds__(THREADS, 1)
mhc_fused_kernel(const float* __restrict__ x,
                 const float* __restrict__ H_pre,
                 const float* __restrict__ H_post,
                 const float* __restrict__ H_res,
                 const float* __restrict__ w,
                 float* __restrict__ out)
{
    const int b = blockIdx.x;
    const int t = threadIdx.x;

    // ---- uniform scalar inputs first (L2-resident after first CTAs) ----
    float hpre0 = __ldg(H_pre + 0), hpre1 = __ldg(H_pre + 1);
    float hpre2 = __ldg(H_pre + 2), hpre3 = __ldg(H_pre + 3);
    float hpost0 = __ldg(H_post + 0), hpost1 = __ldg(H_post + 1);
    float hpost2 = __ldg(H_post + 2), hpost3 = __ldg(H_post + 3);
    float hres[N_DIM * N_DIM];
#pragma unroll
    for (int i = 0; i < N_DIM * N_DIM; i++) hres[i] = __ldg(H_res + i);

    // ---- load this batch row's 4 streams: 1 float4 per stream per thread ----
    const float4* x4 = reinterpret_cast<const float4*>(x) +
                       (size_t)b * N_DIM * F4_PER_ROW;

    float4 v0 = x4[0 * F4_PER_ROW + t];
    float4 v1 = x4[1 * F4_PER_ROW + t];
    float4 v2 = x4[2 * F4_PER_ROW + t];
    float4 v3 = x4[3 * F4_PER_ROW + t];

    // ---- pre-gates (uniform; cheap, redundant per thread) ----
    float pre0 = 1.0f / (1.0f + __expf(-hpre0));
    float pre1 = 1.0f / (1.0f + __expf(-hpre1));
    float pre2 = 1.0f / (1.0f + __expf(-hpre2));
    float pre3 = 1.0f / (1.0f + __expf(-hpre3));

    // ---- aggregate: x_agg = sum_n pre[n] * x[b,n,:] ----
    float4 agg;
    agg.x = pre0*v0.x + pre1*v1.x + pre2*v2.x + pre3*v3.x;
    agg.y = pre0*v0.y + pre1*v1.y + pre2*v2.y + pre3*v3.y;
    agg.z = pre0*v0.z + pre1*v1.z + pre2*v2.z + pre3*v3.z;
    agg.w = pre0*v0.w + pre1*v1.w + pre2*v2.w + pre3*v3.w;

    float ss = agg.x*agg.x + agg.y*agg.y + agg.z*agg.z + agg.w*agg.w;

    // ---- Sinkhorn on 4x4 (uniform) ----
    float P[N_DIM][N_DIM];
#pragma unroll
    for (int i = 0; i < N_DIM; i++)
#pragma unroll
        for (int j = 0; j < N_DIM; j++)
            P[i][j] = __expf(hres[i * N_DIM + j]);

#pragma unroll
    for (int it = 0; it < 3; it++) {
#pragma unroll
        for (int i = 0; i < N_DIM; i++) {
            float inv = 1.0f / (P[i][0] + P[i][1] + P[i][2] + P[i][3] + EPS);
#pragma unroll
            for (int j = 0; j < N_DIM; j++) P[i][j] *= inv;
        }
#pragma unroll
        for (int j = 0; j < N_DIM; j++) {
            float inv = 1.0f / (P[0][j] + P[1][j] + P[2][j] + P[3][j] + EPS);
#pragma unroll
            for (int i = 0; i < N_DIM; i++) P[i][j] *= inv;
        }
    }

    float postm[N_DIM];
    postm[0] = 2.0f / (1.0f + __expf(-hpost0));
    postm[1] = 2.0f / (1.0f + __expf(-hpost1));
    postm[2] = 2.0f / (1.0f + __expf(-hpost2));
    postm[3] = 2.0f / (1.0f + __expf(-hpost3));

    // ---- block reduction of sum(agg^2) over C (32 warps) ----
#pragma unroll
    for (int o = 16; o > 0; o >>= 1)
        ss += __shfl_xor_sync(0xffffffffu, ss, o);

    __shared__ float sred[33];
    if ((t & 31) == 0) sred[t >> 5] = ss;
    __syncthreads();
    if (t < 32) {
        float s = sred[t];
#pragma unroll
        for (int o = 16; o > 0; o >>= 1)
            s += __shfl_xor_sync(0xffffffffu, s, o);
        if (t == 0) sred[32] = s;
    }
    __syncthreads();

    const float rinv = rsqrtf(sred[32] * (1.0f / (float)C_DIM) + EPS);

    // ---- yn = agg * rinv * weight (overwrite agg: not needed after) ----
    const float4 wv = reinterpret_cast<const float4*>(w)[t];
    agg.x = agg.x * rinv * wv.x;
    agg.y = agg.y * rinv * wv.y;
    agg.z = agg.z * rinv * wv.z;
    agg.w = agg.w * rinv * wv.w;

    // ---- out[b,m,:] = sum_n P[m][n]*x[b,n,:] + post[m]*yn ----
    float4* o4 = reinterpret_cast<float4*>(out) + (size_t)b * N_DIM * F4_PER_ROW;

#pragma unroll
    for (int m = 0; m < N_DIM; m++) {
        float4 o;
        o.x = P[m][0]*v0.x + P[m][1]*v1.x + P[m][2]*v2.x + P[m][3]*v3.x + postm[m]*agg.x;
        o.y = P[m][0]*v0.y + P[m][1]*v1.y + P[m][2]*v2.y + P[m][3]*v3.y + postm[m]*agg.y;
        o.z = P[m][0]*v0.z + P[m][1]*v1.z + P[m][2]*v2.z + P[m][3]*v3.z + postm[m]*agg.z;
        o.w = P[m][0]*v0.w + P[m][1]*v1.w + P[m][2]*v2.w + P[m][3]*v3.w + postm[m]*agg.w;
        o4[m * F4_PER_ROW + t] = o;
    }
}

extern "C" void kernel_launch(void* const* d_in, const int* in_sizes, int n_in,
                              void* d_out, int out_size)
{
    const float* x      = (const float*)d_in[0];   // [8192, 4, 4096]
    const float* H_pre  = (const float*)d_in[1];   // [4]
    const float* H_post = (const float*)d_in[2];   // [4]
    const float* H_res  = (const float*)d_in[3];   // [4, 4]
    const float* w      = (const float*)d_in[4];   // [4096]
    float* out          = (float*)d_out;           // [8192, 4, 4096]

    const int B = in_sizes[0] / (N_DIM * C_DIM);   // 8192

    mhc_fused_kernel<<<B, THREADS>>>(x, H_pre, H_post, H_res, w, out);
}